// round 4
// baseline (speedup 1.0000x reference)
#include <cuda_runtime.h>
#include <cstdint>

#define NEXP 8
#define NTOK 8192
#define H    2048
#define I2   4096
#define ID   2048
#define MAXTILES 136
#define PADSLOTS (MAXTILES*128)
#define STG_F 9216            /* floats per stage (A 4608 + B 4608) */
#define SMEM_BYTES 73728      /* 2 stages * 36864 B */

// ---------------- static scratch ----------------
__device__ int    g_count[NEXP];
__device__ int    g_offset[NEXP];
__device__ int    g_ntiles;
__device__ int    g_tile_e[MAXTILES];
__device__ int    g_tok[NEXP*NTOK];
__device__ int    g_slot[NTOK*2];
__device__ float2 g_wv[NTOK];
__device__ __align__(16) float g_xg [(size_t)PADSLOTS*H];
__device__ __align__(16) float g_y  [(size_t)PADSLOTS*ID];
__device__ __align__(16) float g_ob [(size_t)PADSLOTS*H];
__device__ __align__(16) float g_w1r[(size_t)NEXP*I2*H];
__device__ __align__(16) float g_w2r[(size_t)NEXP*H*ID];

// ---------------- helpers ----------------
__device__ __forceinline__ uint32_t smem_u32(const void* p){
    uint32_t a;
    asm("{ .reg .u64 t; cvta.to.shared.u64 t, %1; cvt.u32.u64 %0, t; }" : "=r"(a) : "l"(p));
    return a;
}
__device__ __forceinline__ float tf32_rn(float x){
    uint32_t r; asm("cvt.rna.tf32.f32 %0, %1;" : "=r"(r) : "f"(x));
    return __uint_as_float(r);
}
#define CPA(dst,src) asm volatile("cp.async.cg.shared.global [%0], [%1], 16;" :: "r"(dst), "l"(src))
#define CPC() asm volatile("cp.async.commit_group;" ::: "memory")
#define CPW(n) asm volatile("cp.async.wait_group %0;" :: "n"(n) : "memory")

__device__ __forceinline__ void mma8(float* cc, const float* a, const float* b){
    asm volatile("mma.sync.aligned.m16n8k8.row.col.f32.tf32.tf32.f32 "
        "{%0,%1,%2,%3}, {%4,%5,%6,%7}, {%8,%9}, {%0,%1,%2,%3};"
        : "+f"(cc[0]),"+f"(cc[1]),"+f"(cc[2]),"+f"(cc[3])
        : "r"(__float_as_uint(a[0])),"r"(__float_as_uint(a[1])),
          "r"(__float_as_uint(a[2])),"r"(__float_as_uint(a[3])),
          "r"(__float_as_uint(b[0])),"r"(__float_as_uint(b[1])));
}

// ---------------- small kernels ----------------
__global__ void k_init(){ if (threadIdx.x < NEXP) g_count[threadIdx.x] = 0; }

__global__ void k_gate(const float* __restrict__ x, const float* __restrict__ gw,
                       const float* __restrict__ gb){
    int warp = (blockIdx.x * blockDim.x + threadIdx.x) >> 5;
    int lane = threadIdx.x & 31;
    if (warp >= NTOK) return;
    const float* xr = x + (size_t)warp * H;
    float acc[NEXP];
#pragma unroll
    for (int e = 0; e < NEXP; e++) acc[e] = 0.f;
    for (int i = lane; i < H; i += 32){
        float xv = xr[i];
#pragma unroll
        for (int e = 0; e < NEXP; e++) acc[e] += xv * gw[e*H + i];
    }
#pragma unroll
    for (int e = 0; e < NEXP; e++)
#pragma unroll
        for (int o = 16; o > 0; o >>= 1) acc[e] += __shfl_xor_sync(0xffffffffu, acc[e], o);
    if (lane == 0){
        float lg[NEXP];
#pragma unroll
        for (int e = 0; e < NEXP; e++) lg[e] = acc[e] + gb[e];
        int b0 = 0;
#pragma unroll
        for (int e = 1; e < NEXP; e++) if (lg[e] > lg[b0]) b0 = e;
        int b1 = -1;
#pragma unroll
        for (int e = 0; e < NEXP; e++){ if (e == b0) continue; if (b1 < 0 || lg[e] > lg[b1]) b1 = e; }
        float e1 = expf(lg[b1] - lg[b0]);
        float inv = 1.f / (1.f + e1);
        g_wv[warp] = make_float2(inv, e1 * inv);
        int p0 = atomicAdd(&g_count[b0], 1); g_tok[b0*NTOK + p0] = warp*2 + 0;
        int p1 = atomicAdd(&g_count[b1], 1); g_tok[b1*NTOK + p1] = warp*2 + 1;
    }
}

__global__ void k_scan(){
    if (threadIdx.x == 0){
        int base = 0, nt = 0;
        for (int e = 0; e < NEXP; e++){
            g_offset[e] = base;
            int t = (g_count[e] + 127) >> 7;
            for (int i = 0; i < t; i++) g_tile_e[nt++] = e;
            base += t * 128;
        }
        g_ntiles = nt;
    }
}

__global__ void k_gather(const float* __restrict__ x){
    int e = blockIdx.x, pos0 = blockIdx.y * 8, cnt = g_count[e];
    if (pos0 >= cnt) return;
    int off = g_offset[e];
    for (int r = 0; r < 8; r++){
        int pos = pos0 + r; if (pos >= cnt) break;
        int code = g_tok[e*NTOK + pos], t = code >> 1, slot = off + pos;
        if (threadIdx.x == 0) g_slot[code] = slot;
        const float4* src = (const float4*)(x + (size_t)t * H);
        float4*       dst = (float4*)(g_xg + (size_t)slot * H);
        for (int i = threadIdx.x; i < H/4; i += blockDim.x){
            float4 v = src[i];
            v.x = tf32_rn(v.x); v.y = tf32_rn(v.y); v.z = tf32_rn(v.z); v.w = tf32_rn(v.w);
            dst[i] = v;
        }
    }
}

__global__ void k_round(const float4* __restrict__ W, float4* __restrict__ Wo){
    int i = blockIdx.x * blockDim.x + threadIdx.x;
    float4 v = W[i];
    v.x = tf32_rn(v.x); v.y = tf32_rn(v.y); v.z = tf32_rn(v.z); v.w = tf32_rn(v.w);
    Wo[i] = v;
}

// ---------------- tf32 mma.sync GEMM: C(128x128) = A(128x2048) * B(128x2048)^T ----------------
template<int NY, bool SWIGLU>
__global__ __launch_bounds__(256, 2) void k_mma(const float* __restrict__ Wr,
                                                const float* __restrict__ Bb){
    int tile = blockIdx.y;
    if (tile >= g_ntiles) return;
    int e = g_tile_e[tile], n0 = blockIdx.x * 128;
    extern __shared__ __align__(16) float sm[];
    uint32_t sb = smem_u32(sm);
    int tid = threadIdx.x, lane = tid & 31, wid = tid >> 5;
    int wm = wid >> 2, wn = wid & 3;          // 2 x 4 warp grid
    int fr = lane >> 2, fc = lane & 3;        // fragment row / col components
    const int Nr = SWIGLU ? I2 : H;
    const float* Ag = (SWIGLU ? g_xg : g_y) + (size_t)tile * 128 * 2048;
    const float* Bg = Wr + ((size_t)e * Nr + n0) * 2048;

    float acc[4][4][4];
#pragma unroll
    for (int mt = 0; mt < 4; mt++)
#pragma unroll
        for (int nt = 0; nt < 4; nt++)
#pragma unroll
            for (int q = 0; q < 4; q++) acc[mt][nt][q] = 0.f;

#define ISSUE(s, it) do{ \
        uint32_t sa = sb + (s)*36864u, sbm = sa + 18432u; \
        int k0 = (it)*32; \
        _Pragma("unroll") \
        for (int i = 0; i < 4; i++){ \
            int id = tid + i*256; int row = id >> 3, kc = (id & 7) << 2; \
            CPA(sa  + (uint32_t)(row*36 + kc)*4u, Ag + (size_t)row*2048 + k0 + kc); \
            CPA(sbm + (uint32_t)(row*36 + kc)*4u, Bg + (size_t)row*2048 + k0 + kc); \
        } \
        CPC(); \
    }while(0)

    ISSUE(0, 0);
    ISSUE(1, 1);
    for (int it = 0; it < 64; it++){
        if (it == 63) CPW(0); else CPW(1);
        __syncthreads();
        const float* As = sm + (it & 1) * STG_F;
        const float* Bs = As + 4608;
#pragma unroll
        for (int ks = 0; ks < 4; ks++){
            float af[4][4], bf[4][2];
#pragma unroll
            for (int mt = 0; mt < 4; mt++){
                const float* ap = As + (wm*64 + mt*16 + fr)*36 + ks*8 + fc;
                af[mt][0] = ap[0]; af[mt][1] = ap[288]; af[mt][2] = ap[4]; af[mt][3] = ap[292];
            }
#pragma unroll
            for (int nt = 0; nt < 4; nt++){
                const float* bp = Bs + (wn*32 + nt*8 + fr)*36 + ks*8 + fc;
                bf[nt][0] = bp[0]; bf[nt][1] = bp[4];
            }
#pragma unroll
            for (int mt = 0; mt < 4; mt++)
#pragma unroll
                for (int nt = 0; nt < 4; nt++) mma8(acc[mt][nt], af[mt], bf[nt]);
        }
        __syncthreads();
        if (it + 2 < 64) ISSUE(it & 1, it + 2);
    }

    const float* bias = Bb + (size_t)e * Nr + n0;
    if (SWIGLU){
        float* ysm = sm;   // [128][68]
#pragma unroll
        for (int nt = 0; nt < 4; nt++){
            int cl = wn*32 + nt*8 + 2*fc;
            float bg = bias[cl], bl = bias[cl + 1];
            int yc = cl >> 1;
#pragma unroll
            for (int mt = 0; mt < 4; mt++){
                int row = wm*64 + mt*16 + fr;
                float g0 = acc[mt][nt][0] + bg, l0 = acc[mt][nt][1] + bl;
                float g1 = acc[mt][nt][2] + bg, l1 = acc[mt][nt][3] + bl;
                ysm[row*68 + yc]     = g0 * (1.f/(1.f + expf(-1.702f*g0))) * (l0 + 1.f);
                ysm[(row+8)*68 + yc] = g1 * (1.f/(1.f + expf(-1.702f*g1))) * (l1 + 1.f);
            }
        }
        __syncthreads();
        for (int f = tid; f < 2048; f += 256){
            int row = f >> 4, c4 = f & 15;
            const float* s0 = ysm + row*68 + c4*4;
            float4 v;
            v.x = tf32_rn(s0[0]); v.y = tf32_rn(s0[1]); v.z = tf32_rn(s0[2]); v.w = tf32_rn(s0[3]);
            *((float4*)(g_y + (size_t)(tile*128 + row)*2048 + blockIdx.x*64) + c4) = v;
        }
    } else {
        float* osm = sm;   // [128][132]
#pragma unroll
        for (int nt = 0; nt < 4; nt++){
            int cl = wn*32 + nt*8 + 2*fc;
            float bg = bias[cl], bl = bias[cl + 1];
#pragma unroll
            for (int mt = 0; mt < 4; mt++){
                int row = wm*64 + mt*16 + fr;
                osm[row*132 + cl]       = acc[mt][nt][0] + bg;
                osm[row*132 + cl + 1]   = acc[mt][nt][1] + bl;
                osm[(row+8)*132 + cl]   = acc[mt][nt][2] + bg;
                osm[(row+8)*132 + cl+1] = acc[mt][nt][3] + bl;
            }
        }
        __syncthreads();
        for (int f = tid; f < 4096; f += 256){
            int row = f >> 5, c4 = f & 31;
            const float* s0 = osm + row*132 + c4*4;
            float4 v; v.x = s0[0]; v.y = s0[1]; v.z = s0[2]; v.w = s0[3];
            *((float4*)(g_ob + (size_t)(tile*128 + row)*2048 + n0) + c4) = v;
        }
    }
#undef ISSUE
}

__global__ void k_comb(float* __restrict__ out){
    int gid = blockIdx.x * blockDim.x + threadIdx.x;
    if (gid >= NTOK * (H/4)) return;
    int t = gid / (H/4), c4 = gid % (H/4);
    int s0 = g_slot[2*t], s1 = g_slot[2*t + 1];
    float2 w = g_wv[t];
    float4 a = *((const float4*)(g_ob + (size_t)s0 * H) + c4);
    float4 b = *((const float4*)(g_ob + (size_t)s1 * H) + c4);
    float4 r;
    r.x = w.x*a.x + w.y*b.x; r.y = w.x*a.y + w.y*b.y;
    r.z = w.x*a.z + w.y*b.z; r.w = w.x*a.w + w.y*b.w;
    *((float4*)out + gid) = r;
}

// ---------------- launcher ----------------
extern "C" void kernel_launch(void* const* d_in, const int* in_sizes, int n_in,
                              void* d_out, int out_size){
    const float* x  = (const float*)d_in[0];
    const float* gw = (const float*)d_in[1];
    const float* gb = (const float*)d_in[2];
    const float* w1 = (const float*)d_in[3];
    const float* b1 = (const float*)d_in[4];
    const float* w2 = (const float*)d_in[5];
    const float* b2 = (const float*)d_in[6];
    float* out = (float*)d_out;

    cudaFuncSetAttribute(k_mma<32,true >, cudaFuncAttributeMaxDynamicSharedMemorySize, SMEM_BYTES);
    cudaFuncSetAttribute(k_mma<16,false>, cudaFuncAttributeMaxDynamicSharedMemorySize, SMEM_BYTES);

    k_init<<<1, 32>>>();
    k_gate<<<NTOK/8, 256>>>(x, gw, gb);
    k_scan<<<1, 32>>>();
    k_gather<<<dim3(NEXP, NTOK/8), 256>>>(x);
    k_round<<<65536, 256>>>((const float4*)w1, (float4*)g_w1r);
    k_round<<<32768, 256>>>((const float4*)w2, (float4*)g_w2r);
    k_mma<32,true ><<<dim3(32, MAXTILES), 256, SMEM_BYTES>>>(g_w1r, b1);
    k_mma<16,false><<<dim3(16, MAXTILES), 256, SMEM_BYTES>>>(g_w2r, b2);
    k_comb<<<(NTOK*(H/4) + 255)/256, 256>>>(out);
}

// round 5
// speedup vs baseline: 6.9320x; 6.9320x over previous
#include <cuda_runtime.h>
#include <cstdint>

#define NEXP 8
#define NTOK 8192
#define H    2048
#define I2   4096
#define ID   2048
#define MAXTILES 136
#define PADSLOTS (MAXTILES*128)

typedef unsigned long long u64t;

// ---------------- static scratch ----------------
__device__ int    g_count[NEXP];
__device__ int    g_offset[NEXP];
__device__ int    g_ntiles;
__device__ int    g_tile_e[MAXTILES];
__device__ int    g_tok[NEXP*NTOK];
__device__ int    g_slot[NTOK*2];
__device__ float2 g_wv[NTOK];
__device__ __align__(16) float g_xg[(size_t)PADSLOTS*H];
__device__ __align__(16) float g_y [(size_t)PADSLOTS*ID];
__device__ __align__(16) float g_ob[(size_t)PADSLOTS*H];

// ---------------- f32x2 helpers ----------------
__device__ __forceinline__ u64t pack2(float lo, float hi){
    u64t r; asm("mov.b64 %0, {%1, %2};" : "=l"(r) : "f"(lo), "f"(hi)); return r;
}
__device__ __forceinline__ void unpack2(u64t v, float& lo, float& hi){
    asm("mov.b64 {%0, %1}, %2;" : "=f"(lo), "=f"(hi) : "l"(v));
}
__device__ __forceinline__ void fma2(u64t& c, u64t a, u64t b){
    asm("fma.rn.f32x2 %0, %1, %2, %0;" : "+l"(c) : "l"(a), "l"(b));
}

// ---------------- small kernels ----------------
__global__ void k_init(){ if (threadIdx.x < NEXP) g_count[threadIdx.x] = 0; }

__global__ void k_gate(const float* __restrict__ x, const float* __restrict__ gw,
                       const float* __restrict__ gb){
    int warp = (blockIdx.x * blockDim.x + threadIdx.x) >> 5;
    int lane = threadIdx.x & 31;
    if (warp >= NTOK) return;
    const float* xr = x + (size_t)warp * H;
    float acc[NEXP];
#pragma unroll
    for (int e = 0; e < NEXP; e++) acc[e] = 0.f;
    for (int i = lane; i < H; i += 32){
        float xv = xr[i];
#pragma unroll
        for (int e = 0; e < NEXP; e++) acc[e] += xv * gw[e*H + i];
    }
#pragma unroll
    for (int e = 0; e < NEXP; e++)
#pragma unroll
        for (int o = 16; o > 0; o >>= 1) acc[e] += __shfl_xor_sync(0xffffffffu, acc[e], o);
    if (lane == 0){
        float lg[NEXP];
#pragma unroll
        for (int e = 0; e < NEXP; e++) lg[e] = acc[e] + gb[e];
        int b0 = 0;
#pragma unroll
        for (int e = 1; e < NEXP; e++) if (lg[e] > lg[b0]) b0 = e;
        int b1 = -1;
#pragma unroll
        for (int e = 0; e < NEXP; e++){ if (e == b0) continue; if (b1 < 0 || lg[e] > lg[b1]) b1 = e; }
        float e1 = expf(lg[b1] - lg[b0]);
        float inv = 1.f / (1.f + e1);
        g_wv[warp] = make_float2(inv, e1 * inv);
        int p0 = atomicAdd(&g_count[b0], 1); g_tok[b0*NTOK + p0] = warp*2 + 0;
        int p1 = atomicAdd(&g_count[b1], 1); g_tok[b1*NTOK + p1] = warp*2 + 1;
    }
}

__global__ void k_scan(){
    if (threadIdx.x == 0){
        int base = 0, nt = 0;
        for (int e = 0; e < NEXP; e++){
            g_offset[e] = base;
            int t = (g_count[e] + 127) >> 7;
            for (int i = 0; i < t; i++) g_tile_e[nt++] = e;
            base += t * 128;
        }
        g_ntiles = nt;
    }
}

__global__ void k_gather(const float* __restrict__ x){
    int e = blockIdx.x, pos0 = blockIdx.y * 8, cnt = g_count[e];
    if (pos0 >= cnt) return;
    int off = g_offset[e];
    for (int r = 0; r < 8; r++){
        int pos = pos0 + r; if (pos >= cnt) break;
        int code = g_tok[e*NTOK + pos], t = code >> 1, slot = off + pos;
        if (threadIdx.x == 0) g_slot[code] = slot;
        const float4* src = (const float4*)(x + (size_t)t * H);
        float4*       dst = (float4*)(g_xg + (size_t)slot * H);
        for (int i = threadIdx.x; i < H/4; i += blockDim.x) dst[i] = src[i];
    }
}

// ---------------- f32x2 SIMT GEMM: C(128x128) = A(128xK) * W(128xK)^T ----------------
template<bool SWIGLU>
__global__ __launch_bounds__(256, 2) void k_gemm(const float* __restrict__ Wbase,
                                                 const float* __restrict__ Bbase){
    int tile = blockIdx.x;
    if (tile >= g_ntiles) return;
    const int Nrows = SWIGLU ? I2 : H;
    int e     = g_tile_e[tile];
    int sbase = tile * 128;
    int n0    = blockIdx.y * 128;
    const float* A  = (SWIGLU ? g_xg : g_y) + (size_t)sbase * H;
    const float* W  = Wbase + (size_t)e * Nrows * H + (size_t)n0 * H;
    const float* bs = Bbase + (size_t)e * Nrows + n0;

    __shared__ __align__(16) float As[16][132];
    __shared__ __align__(16) float Bs[16][132];
    int tid = threadIdx.x;
    int tm = (tid >> 4) << 3, tn = (tid & 15) << 3;

    // gmem addresses for this thread's 2 float4 slices per tile
    int f4a = tid*2, f4b = tid*2 + 1;
    int rowa = f4a >> 2, kqa = (f4a & 3) << 2;
    int rowb = f4b >> 2, kqb = (f4b & 3) << 2;
    const float* Apa = A + (size_t)rowa*H + kqa;
    const float* Apb = A + (size_t)rowb*H + kqb;
    const float* Wpa = W + (size_t)rowa*H + kqa;
    const float* Wpb = W + (size_t)rowb*H + kqb;

    u64t acc[8][4];
#pragma unroll
    for (int i = 0; i < 8; i++)
#pragma unroll
        for (int j = 0; j < 4; j++) acc[i][j] = 0ull;

    float4 pa0 = *(const float4*)(Apa);
    float4 pa1 = *(const float4*)(Apb);
    float4 pw0 = *(const float4*)(Wpa);
    float4 pw1 = *(const float4*)(Wpb);

    for (int kt = 0; kt < 128; kt++){
        As[kqa+0][rowa]=pa0.x; As[kqa+1][rowa]=pa0.y; As[kqa+2][rowa]=pa0.z; As[kqa+3][rowa]=pa0.w;
        As[kqb+0][rowb]=pa1.x; As[kqb+1][rowb]=pa1.y; As[kqb+2][rowb]=pa1.z; As[kqb+3][rowb]=pa1.w;
        Bs[kqa+0][rowa]=pw0.x; Bs[kqa+1][rowa]=pw0.y; Bs[kqa+2][rowa]=pw0.z; Bs[kqa+3][rowa]=pw0.w;
        Bs[kqb+0][rowb]=pw1.x; Bs[kqb+1][rowb]=pw1.y; Bs[kqb+2][rowb]=pw1.z; Bs[kqb+3][rowb]=pw1.w;
        __syncthreads();
        if (kt + 1 < 128){
            int k0 = (kt + 1) * 16;
            pa0 = *(const float4*)(Apa + k0);
            pa1 = *(const float4*)(Apb + k0);
            pw0 = *(const float4*)(Wpa + k0);
            pw1 = *(const float4*)(Wpb + k0);
        }
#pragma unroll
        for (int kk = 0; kk < 16; kk++){
            float a[8];
            *(float4*)(a)   = *(const float4*)&As[kk][tm];
            *(float4*)(a+4) = *(const float4*)&As[kk][tm+4];
            ulonglong2 bq0 = *(const ulonglong2*)&Bs[kk][tn];
            ulonglong2 bq1 = *(const ulonglong2*)&Bs[kk][tn+4];
            u64t b2[4] = { bq0.x, bq0.y, bq1.x, bq1.y };
            u64t a2[8];
#pragma unroll
            for (int i = 0; i < 8; i++) a2[i] = pack2(a[i], a[i]);
#pragma unroll
            for (int i = 0; i < 8; i++)
#pragma unroll
                for (int j = 0; j < 4; j++) fma2(acc[i][j], a2[i], b2[j]);
        }
        __syncthreads();
    }

    if (SWIGLU){
#pragma unroll
        for (int i = 0; i < 8; i++){
            int slot = sbase + tm + i;
            float* yr = g_y + (size_t)slot * ID + ((n0 + tn) >> 1);
#pragma unroll
            for (int p = 0; p < 4; p++){
                float cg, cl;
                unpack2(acc[i][p], cg, cl);
                float glu = cg + bs[tn + 2*p];
                float lin = cl + bs[tn + 2*p + 1];
                float s = 1.f / (1.f + expf(-1.702f * glu));
                yr[p] = glu * s * (lin + 1.f);
            }
        }
    } else {
#pragma unroll
        for (int i = 0; i < 8; i++){
            int slot = sbase + tm + i;
            float* orow = g_ob + (size_t)slot * H + n0 + tn;
#pragma unroll
            for (int p = 0; p < 4; p++){
                float c0, c1;
                unpack2(acc[i][p], c0, c1);
                orow[2*p]   = c0 + bs[tn + 2*p];
                orow[2*p+1] = c1 + bs[tn + 2*p + 1];
            }
        }
    }
}

__global__ void k_comb(float* __restrict__ out){
    int gid = blockIdx.x * blockDim.x + threadIdx.x;
    if (gid >= NTOK * (H/4)) return;
    int t = gid / (H/4), c4 = gid % (H/4);
    int s0 = g_slot[2*t], s1 = g_slot[2*t + 1];
    float2 w = g_wv[t];
    float4 a = *((const float4*)(g_ob + (size_t)s0 * H) + c4);
    float4 b = *((const float4*)(g_ob + (size_t)s1 * H) + c4);
    float4 r;
    r.x = w.x*a.x + w.y*b.x; r.y = w.x*a.y + w.y*b.y;
    r.z = w.x*a.z + w.y*b.z; r.w = w.x*a.w + w.y*b.w;
    *((float4*)out + gid) = r;
}

// ---------------- launcher ----------------
extern "C" void kernel_launch(void* const* d_in, const int* in_sizes, int n_in,
                              void* d_out, int out_size){
    const float* x  = (const float*)d_in[0];
    const float* gw = (const float*)d_in[1];
    const float* gb = (const float*)d_in[2];
    const float* w1 = (const float*)d_in[3];
    const float* b1 = (const float*)d_in[4];
    const float* w2 = (const float*)d_in[5];
    const float* b2 = (const float*)d_in[6];
    float* out = (float*)d_out;

    k_init<<<1, 32>>>();
    k_gate<<<NTOK/8, 256>>>(x, gw, gb);
    k_scan<<<1, 32>>>();
    k_gather<<<dim3(NEXP, NTOK/8), 256>>>(x);
    k_gemm<true ><<<dim3(MAXTILES, I2/128), 256>>>(w1, b1);
    k_gemm<false><<<dim3(MAXTILES, H /128), 256>>>(w2, b2);
    k_comb<<<(NTOK*(H/4) + 255)/256, 256>>>(out);
}